// round 14
// baseline (speedup 1.0000x reference)
#include <cuda_runtime.h>
#include <math.h>

#define DD 4096
#define NF4 (DD / 4)          // 1024 float4 per row
#define RPW 4                 // rows per warp (persistent-ish)

__device__ float g_xk[DD], g_xv[DD], g_xr[DD];
__device__ float g_k[DD], g_v[DD], g_r[DD], g_rv[DD];

__device__ __forceinline__ float dot4(float4 a, float4 b) {
    float s = a.x * b.x;
    s = fmaf(a.y, b.y, s);
    s = fmaf(a.z, b.z, s);
    s = fmaf(a.w, b.w, s);
    return s;
}

// grid 16 x 64: one float4 per thread
__global__ void mix_kernel(const float* __restrict__ x,
                           const float* __restrict__ sxx,
                           const float* __restrict__ tmk,
                           const float* __restrict__ tmv,
                           const float* __restrict__ tmr) {
    int i = blockIdx.x * 64 + threadIdx.x;
    if (i >= NF4) return;
    float4 xi = ((const float4*)x)[i];
    float4 si = ((const float4*)sxx)[i];
    float4 k = ((const float4*)tmk)[i];
    float4 v = ((const float4*)tmv)[i];
    float4 r = ((const float4*)tmr)[i];
    float4 ok, ov, orr;
    ok.x = fmaf(xi.x - si.x, k.x, si.x);  ok.y = fmaf(xi.y - si.y, k.y, si.y);
    ok.z = fmaf(xi.z - si.z, k.z, si.z);  ok.w = fmaf(xi.w - si.w, k.w, si.w);
    ov.x = fmaf(xi.x - si.x, v.x, si.x);  ov.y = fmaf(xi.y - si.y, v.y, si.y);
    ov.z = fmaf(xi.z - si.z, v.z, si.z);  ov.w = fmaf(xi.w - si.w, v.w, si.w);
    orr.x = fmaf(xi.x - si.x, r.x, si.x); orr.y = fmaf(xi.y - si.y, r.y, si.y);
    orr.z = fmaf(xi.z - si.z, r.z, si.z); orr.w = fmaf(xi.w - si.w, r.w, si.w);
    ((float4*)g_xk)[i] = ok;
    ((float4*)g_xv)[i] = ov;
    ((float4*)g_xr)[i] = orr;
}

// warp dot of one 16KB row with b; 8-deep manual load batching (as R11 win)
__device__ __forceinline__ float row_dot(const float4* __restrict__ A,
                                         const float4* __restrict__ B,
                                         int lane) {
    float s = 0.f;
    #pragma unroll
    for (int t = 0; t < 4; t++) {
        float4 a[8], b[8];
        #pragma unroll
        for (int u = 0; u < 8; u++) {
            int j = lane + (t * 8 + u) * 32;
            a[u] = __ldg(&A[j]);
            b[u] = __ldg(&B[j]);
        }
        #pragma unroll
        for (int u = 0; u < 8; u++) s += dot4(a[u], b[u]);
    }
    #pragma unroll
    for (int o = 16; o; o >>= 1) s += __shfl_xor_sync(0xffffffffu, s, o);
    return s;
}

// 1-warp block handles RPW consecutive rows of one matrix.
// grid = (DD/RPW, 3), block = 32
__global__ void __launch_bounds__(32) matvec3_kernel(
        const float* __restrict__ wk, const float* __restrict__ wv,
        const float* __restrict__ wr) {
    const int lane = threadIdx.x;
    const int base = blockIdx.x * RPW;
    const int m    = blockIdx.y;

    const float* W = (m == 0) ? wk   : (m == 1) ? wv   : wr;
    const float* B = (m == 0) ? g_xk : (m == 1) ? g_xv : g_xr;
    const float4* Bv = (const float4*)B;

    #pragma unroll
    for (int rr = 0; rr < RPW; rr++) {
        const int row = base + rr;
        float s = row_dot((const float4*)(W + (size_t)row * DD), Bv, lane);
        if (lane == 0) {
            if (m == 0)      g_k[row] = s;
            else if (m == 1) g_v[row] = s;
            else             g_r[row] = 1.0f / (1.0f + expf(-s));
        }
    }
}

// grid 32 x 128. out: [y | x | new_aa | new_bb | new_pp]
__global__ void wkv_kernel(const float* __restrict__ x,
                           const float* __restrict__ aa,
                           const float* __restrict__ bb,
                           const float* __restrict__ pp,
                           const float* __restrict__ t_decay,
                           const float* __restrict__ t_first,
                           float* __restrict__ out) {
    int i = blockIdx.x * 128 + threadIdx.x;
    if (i >= DD) return;
    float k = g_k[i], v = g_v[i], r = g_r[i];
    float ppi = pp[i], aai = aa[i], bbi = bb[i];

    float ww = t_first[i] + k;
    float p  = fmaxf(ppi, ww);
    float e1 = expf(ppi - p);
    float e2 = expf(ww - p);
    float a  = fmaf(e1, aai, e2 * v);
    float b  = fmaf(e1, bbi, e2);
    g_rv[i]  = r * (a / b);

    float ww2 = ppi + t_decay[i];
    float p2  = fmaxf(ww2, k);
    float e1b = expf(ww2 - p2);
    float e2b = expf(k - p2);

    out[DD + i]     = x[i];
    out[2 * DD + i] = fmaf(e1b, aai, e2b * v);
    out[3 * DD + i] = fmaf(e1b, bbi, e2b);
    out[4 * DD + i] = p2;
}

// 1-warp block handles RPW consecutive rows. grid = DD/RPW, block = 32
__global__ void __launch_bounds__(32) matvec_out_kernel(
        const float* __restrict__ wo, float* __restrict__ out) {
    const int lane = threadIdx.x;
    const int base = blockIdx.x * RPW;
    const float4* Bv = (const float4*)g_rv;

    #pragma unroll
    for (int rr = 0; rr < RPW; rr++) {
        const int row = base + rr;
        float s = row_dot((const float4*)(wo + (size_t)row * DD), Bv, lane);
        if (lane == 0) out[row] = s;
    }
}

extern "C" void kernel_launch(void* const* d_in, const int* in_sizes, int n_in,
                              void* d_out, int out_size) {
    const float* x       = (const float*)d_in[0];
    const float* sxx     = (const float*)d_in[1];
    const float* aa      = (const float*)d_in[2];
    const float* bb      = (const float*)d_in[3];
    const float* pp      = (const float*)d_in[4];
    const float* w_key   = (const float*)d_in[5];
    const float* w_val   = (const float*)d_in[6];
    const float* w_rec   = (const float*)d_in[7];
    const float* w_out   = (const float*)d_in[8];
    const float* t_decay = (const float*)d_in[9];
    const float* t_first = (const float*)d_in[10];
    const float* t_mix_k = (const float*)d_in[11];
    const float* t_mix_v = (const float*)d_in[12];
    const float* t_mix_r = (const float*)d_in[13];
    float* out = (float*)d_out;

    mix_kernel<<<16, 64>>>(x, sxx, t_mix_k, t_mix_v, t_mix_r);
    matvec3_kernel<<<dim3(DD / RPW, 3), 32>>>(w_key, w_val, w_rec);
    wkv_kernel<<<32, 128>>>(x, aa, bb, pp, t_decay, t_first, out);
    matvec_out_kernel<<<DD / RPW, 32>>>(w_out, out);
}

// round 15
// speedup vs baseline: 1.2585x; 1.2585x over previous
#include <cuda_runtime.h>
#include <math.h>

#define DD 4096
#define NF4 (DD / 4)          // 1024 float4 per row

__device__ float g_xk[DD], g_xv[DD], g_xr[DD];
__device__ float g_k[DD], g_v[DD], g_r[DD], g_rv[DD];

__device__ __forceinline__ float dot4(float4 a, float4 b) {
    float s = a.x * b.x;
    s = fmaf(a.y, b.y, s);
    s = fmaf(a.z, b.z, s);
    s = fmaf(a.w, b.w, s);
    return s;
}

// grid 16 x 64: one float4 per thread
__global__ void mix_kernel(const float* __restrict__ x,
                           const float* __restrict__ sxx,
                           const float* __restrict__ tmk,
                           const float* __restrict__ tmv,
                           const float* __restrict__ tmr) {
    int i = blockIdx.x * 64 + threadIdx.x;
    if (i >= NF4) return;
    float4 xi = ((const float4*)x)[i];
    float4 si = ((const float4*)sxx)[i];
    float4 k = ((const float4*)tmk)[i];
    float4 v = ((const float4*)tmv)[i];
    float4 r = ((const float4*)tmr)[i];
    float4 ok, ov, orr;
    ok.x = fmaf(xi.x - si.x, k.x, si.x);  ok.y = fmaf(xi.y - si.y, k.y, si.y);
    ok.z = fmaf(xi.z - si.z, k.z, si.z);  ok.w = fmaf(xi.w - si.w, k.w, si.w);
    ov.x = fmaf(xi.x - si.x, v.x, si.x);  ov.y = fmaf(xi.y - si.y, v.y, si.y);
    ov.z = fmaf(xi.z - si.z, v.z, si.z);  ov.w = fmaf(xi.w - si.w, v.w, si.w);
    orr.x = fmaf(xi.x - si.x, r.x, si.x); orr.y = fmaf(xi.y - si.y, r.y, si.y);
    orr.z = fmaf(xi.z - si.z, r.z, si.z); orr.w = fmaf(xi.w - si.w, r.w, si.w);
    ((float4*)g_xk)[i] = ok;
    ((float4*)g_xv)[i] = ov;
    ((float4*)g_xr)[i] = orr;
}

// warp dot of one 16KB row with b.
// 8-deep batching on the DRAM (weight) stream only; b consumed on the fly
// (L1-resident, ~39cyc hits). Two accumulators to shorten FMA chains.
__device__ __forceinline__ float row_dot(const float4* __restrict__ A,
                                         const float4* __restrict__ B,
                                         int lane) {
    float s0 = 0.f, s1 = 0.f;
    #pragma unroll
    for (int t = 0; t < 4; t++) {
        float4 a[8];
        #pragma unroll
        for (int u = 0; u < 8; u++)
            a[u] = __ldg(&A[lane + (t * 8 + u) * 32]);
        #pragma unroll
        for (int u = 0; u < 8; u += 2) {
            float4 b0 = __ldg(&B[lane + (t * 8 + u) * 32]);
            float4 b1 = __ldg(&B[lane + (t * 8 + u + 1) * 32]);
            s0 += dot4(a[u], b0);
            s1 += dot4(a[u + 1], b1);
        }
    }
    float s = s0 + s1;
    #pragma unroll
    for (int o = 16; o; o >>= 1) s += __shfl_xor_sync(0xffffffffu, s, o);
    return s;
}

// one 1-warp block per (row, matrix). grid = (DD, 3), block = 32
__global__ void __launch_bounds__(32) matvec3_kernel(
        const float* __restrict__ wk, const float* __restrict__ wv,
        const float* __restrict__ wr) {
    const int lane = threadIdx.x;
    const int row  = blockIdx.x;
    const int m    = blockIdx.y;

    const float* W = (m == 0) ? wk   : (m == 1) ? wv   : wr;
    const float* B = (m == 0) ? g_xk : (m == 1) ? g_xv : g_xr;

    float s = row_dot((const float4*)(W + (size_t)row * DD), (const float4*)B, lane);

    if (lane == 0) {
        if (m == 0)      g_k[row] = s;
        else if (m == 1) g_v[row] = s;
        else             g_r[row] = 1.0f / (1.0f + expf(-s));
    }
}

// grid 32 x 128. out: [y | x | new_aa | new_bb | new_pp]
__global__ void wkv_kernel(const float* __restrict__ x,
                           const float* __restrict__ aa,
                           const float* __restrict__ bb,
                           const float* __restrict__ pp,
                           const float* __restrict__ t_decay,
                           const float* __restrict__ t_first,
                           float* __restrict__ out) {
    int i = blockIdx.x * 128 + threadIdx.x;
    if (i >= DD) return;
    float k = g_k[i], v = g_v[i], r = g_r[i];
    float ppi = pp[i], aai = aa[i], bbi = bb[i];

    float ww = t_first[i] + k;
    float p  = fmaxf(ppi, ww);
    float e1 = expf(ppi - p);
    float e2 = expf(ww - p);
    float a  = fmaf(e1, aai, e2 * v);
    float b  = fmaf(e1, bbi, e2);
    g_rv[i]  = r * (a / b);

    float ww2 = ppi + t_decay[i];
    float p2  = fmaxf(ww2, k);
    float e1b = expf(ww2 - p2);
    float e2b = expf(k - p2);

    out[DD + i]     = x[i];
    out[2 * DD + i] = fmaf(e1b, aai, e2b * v);
    out[3 * DD + i] = fmaf(e1b, bbi, e2b);
    out[4 * DD + i] = p2;
}

// one 1-warp block per row. grid = DD, block = 32
__global__ void __launch_bounds__(32) matvec_out_kernel(
        const float* __restrict__ wo, float* __restrict__ out) {
    const int lane = threadIdx.x;
    const int row  = blockIdx.x;

    float s = row_dot((const float4*)(wo + (size_t)row * DD),
                      (const float4*)g_rv, lane);

    if (lane == 0) out[row] = s;
}

extern "C" void kernel_launch(void* const* d_in, const int* in_sizes, int n_in,
                              void* d_out, int out_size) {
    const float* x       = (const float*)d_in[0];
    const float* sxx     = (const float*)d_in[1];
    const float* aa      = (const float*)d_in[2];
    const float* bb      = (const float*)d_in[3];
    const float* pp      = (const float*)d_in[4];
    const float* w_key   = (const float*)d_in[5];
    const float* w_val   = (const float*)d_in[6];
    const float* w_rec   = (const float*)d_in[7];
    const float* w_out   = (const float*)d_in[8];
    const float* t_decay = (const float*)d_in[9];
    const float* t_first = (const float*)d_in[10];
    const float* t_mix_k = (const float*)d_in[11];
    const float* t_mix_v = (const float*)d_in[12];
    const float* t_mix_r = (const float*)d_in[13];
    float* out = (float*)d_out;

    mix_kernel<<<16, 64>>>(x, sxx, t_mix_k, t_mix_v, t_mix_r);
    matvec3_kernel<<<dim3(DD, 3), 32>>>(w_key, w_val, w_rec);
    wkv_kernel<<<32, 128>>>(x, aa, bb, pp, t_decay, t_first, out);
    matvec_out_kernel<<<DD, 32>>>(w_out, out);
}